// round 7
// baseline (speedup 1.0000x reference)
#include <cuda_runtime.h>

// TokenEmbedding segment-sum, SINGLE fused launch:
//   bids [0, 256):   producers — scatter packed bounds seg2[b][t] =
//                    (start[t], start[t+1]) from sorted w2t, then release
//                    g_done (one atomicAdd per block).
//   bids [256, ...): consumers — spin (thread 0) until g_done==256, then run
//                    the proven R4 loop: 128 threads, 2 float4 columns each,
//                    one int2 bounds load, __ldcs/__stcs streaming.
// Deadlock-safe: all 256 producer blocks fit in wave 1 (n_conc ~ 2368).
// Replay-safe: last consumer resets g_done/g_finished for the next replay.

#define B_DIM 8
#define L_DIM 4096
#define H_DIM 1024
#define H4   (H_DIM / 4)   // 256 float4 per row
#define HALF 128           // consumer threads; each owns 2 float4 columns
#define NA   256           // producer blocks (32768 wordpieces / 128)
#define NB   (B_DIM * L_DIM)

__device__ int2 g_seg2[B_DIM][L_DIM];  // {start[t], start[t+1]}
__device__ int  g_done;                // producers finished (zero-init)
__device__ int  g_finished;            // consumers finished (zero-init)

__global__ __launch_bounds__(HALF, 16) void token_segsum_fused(
    const float* __restrict__ x,      // [B, L, H]
    const int*   __restrict__ w2t,    // [B, L] sorted per row
    float*       __restrict__ out)    // [B, L, H]
{
    if (blockIdx.x < NA) {
        // ---------------- producer: segment bounds ----------------
        const int wg = blockIdx.x * HALF + threadIdx.x;  // 0..32767
        const int b  = wg >> 12;          // / L_DIM
        const int w  = wg & (L_DIM - 1);

        const int* idx = w2t + (size_t)b * L_DIM;
        const int cur  = __ldg(idx + w);
        const int prev = (w > 0) ? __ldg(idx + w - 1) : -1;

        for (int t = prev + 1; t <= cur; ++t) {
            g_seg2[b][t].x = w;                  // lo of token t
            if (t >= 1) g_seg2[b][t - 1].y = w;  // hi of token t-1
        }
        if (w == L_DIM - 1) {
            for (int t = cur + 1; t <= L_DIM; ++t) {
                if (t < L_DIM) g_seg2[b][t].x = L_DIM;
                g_seg2[b][t - 1].y = L_DIM;
            }
        }

        __threadfence();
        __syncthreads();
        if (threadIdx.x == 0) atomicAdd(&g_done, 1);  // release
        return;
    }

    // ---------------- consumer: one token per block ----------------
    const int id = blockIdx.x - NA;
    const int b  = id >> 12;           // / L_DIM
    const int t  = id & (L_DIM - 1);

    if (threadIdx.x == 0) {
        while (*(volatile int*)&g_done < NA) { }  // acquire spin
    }
    __syncthreads();
    __threadfence();

    const int2 bnd = __ldg(&g_seg2[b][t]);
    const int lo = bnd.x;
    const int hi = bnd.y;

    const int c = threadIdx.x;  // float4 column 0..127 (also owns c+128)
    const float4* __restrict__ rows =
        reinterpret_cast<const float4*>(x + (size_t)b * L_DIM * H_DIM);

    float4 a0 = make_float4(0.f, 0.f, 0.f, 0.f);
    float4 a1 = a0;

    for (int w = lo; w < hi; ++w) {
        const float4* r = rows + (size_t)w * H4;
        float4 v0 = __ldcs(r + c);
        float4 v1 = __ldcs(r + c + HALF);
        a0.x += v0.x; a0.y += v0.y; a0.z += v0.z; a0.w += v0.w;
        a1.x += v1.x; a1.y += v1.y; a1.z += v1.z; a1.w += v1.w;
    }

    float4* __restrict__ orow =
        reinterpret_cast<float4*>(out + ((size_t)b * L_DIM + t) * H_DIM);
    __stcs(orow + c,        a0);
    __stcs(orow + c + HALF, a1);

    // ---- replay-safe counter reset by the last finishing consumer ----
    __syncthreads();
    if (threadIdx.x == 0) {
        int prev = atomicAdd(&g_finished, 1);
        if (prev == NB - 1) {   // everyone (incl. all spinners) is done
            g_finished = 0;
            g_done     = 0;
        }
    }
}

extern "C" void kernel_launch(void* const* d_in, const int* in_sizes, int n_in,
                              void* d_out, int out_size)
{
    const float* x   = (const float*)d_in[0];   // sequence_output [B,L,H] fp32
    const int*   w2t = (const int*)  d_in[1];   // wordpiece_to_token [B,L] int32
    float*       out = (float*)d_out;           // [B,L,H] fp32

    token_segsum_fused<<<NA + NB, HALF>>>(x, w2t, out);
}

// round 8
// speedup vs baseline: 1.1469x; 1.1469x over previous
#include <cuda_runtime.h>

// TokenEmbedding segment-sum, two-phase (champion R4 shape + L2 prefetch):
//   Phase A: scatter packed bounds seg2[b][t] = (start[t], start[t+1]).
//   Phase B: one CTA per (b, t), 128 threads, 2 float4 columns each.
//            NEW: before the (dependent) bounds load, the block issues
//            prefetch.global.L2 for row w==t. Across the grid this prefetches
//            every input row exactly once (t <-> w bijection), overlapping
//            the row DRAM fetch with the bounds-load latency instead of
//            serializing after it.

#define B_DIM 8
#define L_DIM 4096
#define H_DIM 1024
#define H4   (H_DIM / 4)   // 256 float4 per row
#define TB   128           // phase-B threads; each owns 2 float4 columns

// packed bounds: seg2[b][t] = { start[t], start[t+1] }
__device__ int2 g_seg2[B_DIM][L_DIM];

__global__ __launch_bounds__(256) void seg_bounds_kernel(
    const int* __restrict__ w2t)      // [B, L] sorted per row
{
    const int b = blockIdx.y;
    const int w = blockIdx.x * blockDim.x + threadIdx.x;
    if (w >= L_DIM) return;

    const int* idx = w2t + (size_t)b * L_DIM;
    const int cur  = __ldg(idx + w);
    const int prev = (w > 0) ? __ldg(idx + w - 1) : -1;

    for (int t = prev + 1; t <= cur; ++t) {
        g_seg2[b][t].x = w;                  // lo of token t
        if (t >= 1) g_seg2[b][t - 1].y = w;  // hi of token t-1
    }
    if (w == L_DIM - 1) {
        for (int t = cur + 1; t <= L_DIM; ++t) {
            if (t < L_DIM) g_seg2[b][t].x = L_DIM;
            g_seg2[b][t - 1].y = L_DIM;
        }
    }
}

__global__ __launch_bounds__(TB) void token_segsum_kernel(
    const float* __restrict__ x,      // [B, L, H]
    float*       __restrict__ out)    // [B, L, H]
{
    const int t = blockIdx.x;   // token id
    const int b = blockIdx.y;   // batch

    const float* __restrict__ xb = x + (size_t)b * L_DIM * H_DIM;

    // --- speculative L2 prefetch of row w==t (collectively exact coverage) ---
    // row = 4096 B = 32 x 128B lines; threads 0..31 prefetch one line each.
    if (threadIdx.x < 32) {
        const float* p = xb + (size_t)t * H_DIM + threadIdx.x * 32;
        asm volatile("prefetch.global.L2 [%0];" :: "l"(p));
    }

    // dependent metadata load (L2-hot, 8B broadcast)
    const int2 bnd = __ldg(&g_seg2[b][t]);
    const int lo = bnd.x;
    const int hi = bnd.y;

    const int c = threadIdx.x;  // float4 column 0..127 (also owns c+128)
    const float4* __restrict__ rows = reinterpret_cast<const float4*>(xb);

    float4 a0 = make_float4(0.f, 0.f, 0.f, 0.f);
    float4 a1 = a0;

    for (int w = lo; w < hi; ++w) {
        const float4* r = rows + (size_t)w * H4;
        float4 v0 = __ldcs(r + c);
        float4 v1 = __ldcs(r + c + TB);
        a0.x += v0.x; a0.y += v0.y; a0.z += v0.z; a0.w += v0.w;
        a1.x += v1.x; a1.y += v1.y; a1.z += v1.z; a1.w += v1.w;
    }

    float4* __restrict__ orow =
        reinterpret_cast<float4*>(out + ((size_t)b * L_DIM + t) * H_DIM);
    __stcs(orow + c,      a0);
    __stcs(orow + c + TB, a1);
}

extern "C" void kernel_launch(void* const* d_in, const int* in_sizes, int n_in,
                              void* d_out, int out_size)
{
    const float* x   = (const float*)d_in[0];   // sequence_output [B,L,H] fp32
    const int*   w2t = (const int*)  d_in[1];   // wordpiece_to_token [B,L] int32
    float*       out = (float*)d_out;           // [B,L,H] fp32

    dim3 gridA(L_DIM / 256, B_DIM);
    seg_bounds_kernel<<<gridA, 256>>>(w2t);

    dim3 gridB(L_DIM, B_DIM);
    token_segsum_kernel<<<gridB, TB>>>(x, out);
}